// round 1
// baseline (speedup 1.0000x reference)
#include <cuda_runtime.h>
#include <cuda_bf16.h>
#include <cstdint>

// Problem constants
#define BATCH   8192
#define IDIM    768
#define JDIM    768
#define GRID_G  5
#define KDIM    (IDIM * GRID_G)   // 3840

// GEMM tiling
#define BM 128
#define BN 128
#define BK 32
#define ASTR (BK + 4)    // 36: conflict-free A fragment loads
#define BSTR (BN + 4)    // 132: conflict-free B fragment loads
#define GEMM_THREADS 256
#define SMEM_FLOATS (2 * BM * ASTR + 2 * BK * BSTR)
#define SMEM_BYTES  (SMEM_FLOATS * 4)

// Scratch (device globals -- no allocation allowed)
__device__ float g_basis[(size_t)BATCH * KDIM];   // 126 MB
__device__ float g_wp[(size_t)KDIM * JDIM];       // 11.8 MB
__device__ float g_bias[JDIM];

__device__ __forceinline__ float to_tf32(float x) {
    uint32_t u;
    asm("cvt.rna.tf32.f32 %0, %1;" : "=r"(u) : "f"(x));
    return __uint_as_float(u);
}

__device__ __forceinline__ void cp16(float* dst, const float* src) {
    uint32_t d = (uint32_t)__cvta_generic_to_shared(dst);
    asm volatile("cp.async.cg.shared.global [%0], [%1], 16;\n" :: "r"(d), "l"(src));
}
__device__ __forceinline__ void cp_commit() {
    asm volatile("cp.async.commit_group;\n" ::: "memory");
}
template <int N>
__device__ __forceinline__ void cp_wait() {
    asm volatile("cp.async.wait_group %0;\n" :: "n"(N) : "memory");
}

__device__ __forceinline__ void mma_tf32(float c[4], const uint32_t a[4], const uint32_t b[2]) {
    asm volatile(
        "mma.sync.aligned.m16n8k8.row.col.f32.tf32.tf32.f32 "
        "{%0,%1,%2,%3}, {%4,%5,%6,%7}, {%8,%9}, {%0,%1,%2,%3};\n"
        : "+f"(c[0]), "+f"(c[1]), "+f"(c[2]), "+f"(c[3])
        : "r"(a[0]), "r"(a[1]), "r"(a[2]), "r"(a[3]), "r"(b[0]), "r"(b[1]));
}

// ---------------------------------------------------------------------------
// Kernel 1: pack weights  Wp[(i*5+g)*J + j] = tf32(coeffs[i,j,g] * scale[i,j])
// ---------------------------------------------------------------------------
__global__ void pack_kernel(const float* __restrict__ coeffs,
                            const float* __restrict__ scale) {
    int idx = blockIdx.x * blockDim.x + threadIdx.x;   // over I*J
    if (idx >= IDIM * JDIM) return;
    int i = idx / JDIM;
    int j = idx - i * JDIM;
    float s = scale[idx];
    const float* c = coeffs + (size_t)idx * GRID_G;
    #pragma unroll
    for (int g = 0; g < GRID_G; ++g) {
        g_wp[(size_t)(i * GRID_G + g) * JDIM + j] = to_tf32(c[g] * s);
    }
}

// ---------------------------------------------------------------------------
// Kernel 2: bias[j] = sum_i shift[i,j]
// ---------------------------------------------------------------------------
__global__ void bias_kernel(const float* __restrict__ shift) {
    int j = blockIdx.x * blockDim.x + threadIdx.x;
    if (j >= JDIM) return;
    float s = 0.f;
    #pragma unroll 4
    for (int i = 0; i < IDIM; ++i) s += shift[(size_t)i * JDIM + j];
    g_bias[j] = s;
}

// ---------------------------------------------------------------------------
// Kernel 3: basis[b, i*5+g] = tf32(exp(-5 * (tanh(x[b,i]) - grid[g])^2))
// ---------------------------------------------------------------------------
__global__ void basis_kernel(const float* __restrict__ x) {
    int idx = blockIdx.x * blockDim.x + threadIdx.x;   // over BATCH*IDIM
    if (idx >= BATCH * IDIM) return;
    float t = tanhf(x[idx]);
    int b = idx / IDIM;
    int i = idx - b * IDIM;
    float* dst = g_basis + (size_t)b * KDIM + i * GRID_G;
    #pragma unroll
    for (int g = 0; g < GRID_G; ++g) {
        float gv = -1.0f + 0.5f * (float)g;
        float d = t - gv;
        dst[g] = to_tf32(__expf(-5.0f * d * d));
    }
}

// ---------------------------------------------------------------------------
// Kernel 4: C[b,j] = sum_k basis[b,k] * Wp[k,j] + bias[j]
// TF32 mma.sync m16n8k8, 128x128x32 CTA tile, cp.async double buffer.
// ---------------------------------------------------------------------------
__global__ __launch_bounds__(GEMM_THREADS, 2)
void gemm_kernel(float* __restrict__ C) {
    extern __shared__ float smem[];
    // layout: As[0], As[1], Bs[0], Bs[1]
    float* AsBase = smem;
    float* BsBase = smem + 2 * BM * ASTR;

    const int tid  = threadIdx.x;
    const int lane = tid & 31;
    const int wid  = tid >> 5;
    const int wm   = (wid >> 2) * 64;   // warp row offset within CTA tile
    const int wn   = (wid & 3) * 32;    // warp col offset
    const int bm0  = blockIdx.y * BM;
    const int bn0  = blockIdx.x * BN;

    // staging indices
    const int arow = tid >> 3;          // 0..31 (+32q)
    const int ac4  = (tid & 7) * 4;     // 0..28
    const int brow = tid >> 5;          // 0..7 (+8q)
    const int bc4  = (tid & 31) * 4;    // 0..124

    float acc[4][4][4];
    #pragma unroll
    for (int mt = 0; mt < 4; ++mt)
        #pragma unroll
        for (int nt = 0; nt < 4; ++nt)
            #pragma unroll
            for (int r = 0; r < 4; ++r) acc[mt][nt][r] = 0.f;

    const int NT = KDIM / BK;   // 120

    // stage tile 0 into buffer 0
    {
        const float* asrc = g_basis + (size_t)(bm0 + arow) * KDIM + ac4;
        float* adst = AsBase + arow * ASTR + ac4;
        #pragma unroll
        for (int q = 0; q < 4; ++q) cp16(adst + q * 32 * ASTR, asrc + (size_t)q * 32 * KDIM);
        const float* bsrc = g_wp + (size_t)brow * JDIM + bn0 + bc4;
        float* bdst = BsBase + brow * BSTR + bc4;
        #pragma unroll
        for (int q = 0; q < 4; ++q) cp16(bdst + q * 8 * BSTR, bsrc + (size_t)q * 8 * JDIM);
        cp_commit();
    }

    for (int kt = 0; kt < NT; ++kt) {
        const int cur = kt & 1;
        if (kt + 1 < NT) {
            const int nxt = cur ^ 1;
            const int kk = (kt + 1) * BK;
            const float* asrc = g_basis + (size_t)(bm0 + arow) * KDIM + kk + ac4;
            float* adst = AsBase + nxt * (BM * ASTR) + arow * ASTR + ac4;
            #pragma unroll
            for (int q = 0; q < 4; ++q) cp16(adst + q * 32 * ASTR, asrc + (size_t)q * 32 * KDIM);
            const float* bsrc = g_wp + (size_t)(kk + brow) * JDIM + bn0 + bc4;
            float* bdst = BsBase + nxt * (BK * BSTR) + brow * BSTR + bc4;
            #pragma unroll
            for (int q = 0; q < 4; ++q) cp16(bdst + q * 8 * BSTR, bsrc + (size_t)q * 8 * JDIM);
            cp_commit();
            cp_wait<1>();   // tile kt complete, kt+1 may be in flight
        } else {
            cp_wait<0>();
        }
        __syncthreads();

        const float* as = AsBase + cur * (BM * ASTR);
        const float* bs = BsBase + cur * (BK * BSTR);

        #pragma unroll
        for (int ks = 0; ks < BK / 8; ++ks) {
            const int k0 = ks * 8;
            uint32_t af[4][4];
            #pragma unroll
            for (int mt = 0; mt < 4; ++mt) {
                const float* ap = as + (wm + mt * 16 + (lane >> 2)) * ASTR + k0 + (lane & 3);
                af[mt][0] = __float_as_uint(ap[0]);
                af[mt][1] = __float_as_uint(ap[8 * ASTR]);
                af[mt][2] = __float_as_uint(ap[4]);
                af[mt][3] = __float_as_uint(ap[8 * ASTR + 4]);
            }
            uint32_t bf[4][2];
            #pragma unroll
            for (int nt = 0; nt < 4; ++nt) {
                const float* bp = bs + (k0 + (lane & 3)) * BSTR + wn + nt * 8 + (lane >> 2);
                bf[nt][0] = __float_as_uint(bp[0]);
                bf[nt][1] = __float_as_uint(bp[4 * BSTR]);
            }
            #pragma unroll
            for (int mt = 0; mt < 4; ++mt)
                #pragma unroll
                for (int nt = 0; nt < 4; ++nt)
                    mma_tf32(acc[mt][nt], af[mt], bf[nt]);
        }
        __syncthreads();
    }

    // epilogue: add bias, write out
    #pragma unroll
    for (int mt = 0; mt < 4; ++mt) {
        const int r0 = bm0 + wm + mt * 16 + (lane >> 2);
        #pragma unroll
        for (int nt = 0; nt < 4; ++nt) {
            const int c0 = bn0 + wn + nt * 8 + 2 * (lane & 3);
            const float bv0 = g_bias[c0];
            const float bv1 = g_bias[c0 + 1];
            float2 v0 = make_float2(acc[mt][nt][0] + bv0, acc[mt][nt][1] + bv1);
            float2 v1 = make_float2(acc[mt][nt][2] + bv0, acc[mt][nt][3] + bv1);
            *reinterpret_cast<float2*>(C + (size_t)r0 * JDIM + c0) = v0;
            *reinterpret_cast<float2*>(C + (size_t)(r0 + 8) * JDIM + c0) = v1;
        }
    }
}

// ---------------------------------------------------------------------------
extern "C" void kernel_launch(void* const* d_in, const int* in_sizes, int n_in,
                              void* d_out, int out_size) {
    const float* x      = (const float*)d_in[0];
    const float* coeffs = (const float*)d_in[1];
    const float* scale  = (const float*)d_in[2];
    const float* shift  = (const float*)d_in[3];
    float* out = (float*)d_out;

    pack_kernel<<<(IDIM * JDIM + 255) / 256, 256>>>(coeffs, scale);
    bias_kernel<<<(JDIM + 255) / 256, 256>>>(shift);
    basis_kernel<<<(BATCH * IDIM + 255) / 256, 256>>>(x);

    cudaFuncSetAttribute(gemm_kernel, cudaFuncAttributeMaxDynamicSharedMemorySize, SMEM_BYTES);
    gemm_kernel<<<dim3(JDIM / BN, BATCH / BM), GEMM_THREADS, SMEM_BYTES>>>(out);
}